// round 3
// baseline (speedup 1.0000x reference)
#include <cuda_runtime.h>

#define BATCH 8
#define CH 3
#define H 1024
#define W 1280
#define HW (H * W)
#define EPS 1e-7f
#define MIN_DEPTH 10.0f
#define MAX_DEPTH 255.0f

#define TILE_W 128
#define TILE_H 8
#define SRC_ROWS 10          // rows [yt-1 .. yt+8]
#define SRC_COLS 136         // cols [xt-2 .. xt+133] (133 used, padded)

// Per-batch fused parameters: M (9 floats, row-major 3x3) + c (3 floats)
__device__ float g_MC[BATCH * 12];

__global__ void setup_params_kernel(const float* __restrict__ srcK,
                                    const float* __restrict__ tgtK,
                                    const float* __restrict__ tvec) {
    int b = threadIdx.x;
    if (b >= BATCH) return;
    const float* S = srcK + b * 16;
    const float* T = tgtK + b * 16;
    const float* t = tvec + b * 3;

    float a00 = S[0], a01 = S[1], a02 = S[2];
    float a10 = S[4], a11 = S[5], a12 = S[6];
    float a20 = S[8], a21 = S[9], a22 = S[10];
    float det = a00 * (a11 * a22 - a12 * a21)
              - a01 * (a10 * a22 - a12 * a20)
              + a02 * (a10 * a21 - a11 * a20);
    float id = 1.0f / det;
    float i00 = (a11 * a22 - a12 * a21) * id;
    float i01 = (a02 * a21 - a01 * a22) * id;
    float i02 = (a01 * a12 - a02 * a11) * id;
    float i10 = (a12 * a20 - a10 * a22) * id;
    float i11 = (a00 * a22 - a02 * a20) * id;
    float i12 = (a02 * a10 - a00 * a12) * id;
    float i20 = (a10 * a21 - a11 * a20) * id;
    float i21 = (a01 * a20 - a00 * a21) * id;
    float i22 = (a00 * a11 - a01 * a10) * id;

    float k00 = T[0], k01 = T[1], k02 = T[2];
    float k10 = T[4], k11 = T[5], k12 = T[6];
    float k20 = T[8], k21 = T[9], k22 = T[10];

    float* P = g_MC + b * 12;
    P[0] = k00 * i00 + k01 * i10 + k02 * i20;
    P[1] = k00 * i01 + k01 * i11 + k02 * i21;
    P[2] = k00 * i02 + k01 * i12 + k02 * i22;
    P[3] = k10 * i00 + k11 * i10 + k12 * i20;
    P[4] = k10 * i01 + k11 * i11 + k12 * i21;
    P[5] = k10 * i02 + k11 * i12 + k12 * i22;
    P[6] = k20 * i00 + k21 * i10 + k22 * i20;
    P[7] = k20 * i01 + k21 * i11 + k22 * i21;
    P[8] = k20 * i02 + k21 * i12 + k22 * i22;
    P[9]  = k00 * t[0] + k01 * t[1] + k02 * t[2];
    P[10] = k10 * t[0] + k11 * t[1] + k12 * t[2];
    P[11] = k20 * t[0] + k21 * t[1] + k22 * t[2];
}

// grid: (W/TILE_W, H/TILE_H, BATCH), block 256.
// Each thread processes a 4-px quad: lane qx = tid%32 -> x quad, row = tid/32.
__global__ __launch_bounds__(256) void synth_kernel(const float* __restrict__ img,
                                                    const float* __restrict__ disp,
                                                    float* __restrict__ out) {
    __shared__ float sImg[CH][SRC_ROWS][SRC_COLS];
    __shared__ float sP[12];

    const int b  = blockIdx.z;
    const int yt = blockIdx.y * TILE_H;          // tile top output row
    const int xt = blockIdx.x * TILE_W;          // tile left output col
    const int tid = threadIdx.x;

    const int ys0 = yt - 1;                      // staged row 0 -> global row ys0
    const int xs0 = xt - 2;                      // staged col 0 -> global col xs0

    if (tid < 12) sP[tid] = g_MC[b * 12 + tid];

    // ---- Stage source tile (+halo), border-clamped ----
    const float* imb = img + (size_t)b * CH * HW;
#pragma unroll
    for (int ch = 0; ch < CH; ch++) {
        const float* p = imb + ch * HW;
        for (int idx = tid; idx < SRC_ROWS * SRC_COLS; idx += 256) {
            int r = idx / SRC_COLS;
            int c = idx - r * SRC_COLS;
            int gy = min(max(ys0 + r, 0), H - 1);
            int gx = min(max(xs0 + c, 0), W - 1);
            sImg[ch][r][c] = __ldg(p + gy * W + gx);
        }
    }
    __syncthreads();

    const float m0 = sP[0], m1 = sP[1], m2 = sP[2];
    const float m3 = sP[3], m4 = sP[4], m5 = sP[5];
    const float m6 = sP[6], m7 = sP[7], m8 = sP[8];
    const float c0 = sP[9], c1 = sP[10], c2 = sP[11];

    const int qx  = tid & 31;                    // quad index along x
    const int row = tid >> 5;                    // output row within tile
    const int y   = yt + row;
    const int xbase = xt + qx * 4;

    const int rowoff = y * W + xbase;
    const float4 d4 = *(const float4*)(disp + (size_t)b * HW + rowoff);
    const float* dv = (const float*)&d4;

    const float min_disp = 1.0f / MAX_DEPTH;
    const float max_disp = 1.0f / MIN_DEPTH;

    const float fy = (float)y;
    const float py_x = m1 * fy + m2;
    const float py_y = m4 * fy + m5;
    const float py_z = m7 * fy + m8;

    float4 r0, r1, r2;
    float* acc0 = (float*)&r0;
    float* acc1 = (float*)&r1;
    float* acc2 = (float*)&r2;

#pragma unroll
    for (int i = 0; i < 4; i++) {
        float depth = 1.0f / (min_disp + (max_disp - min_disp) * dv[i]);
        float fx = (float)(xbase + i);
        float cpx = depth * (m0 * fx + py_x) + c0;
        float cpy = depth * (m3 * fx + py_y) + c1;
        float cpz = depth * (m6 * fx + py_z) + c2;

        float inv_z = 1.0f / (cpz + EPS);
        float pcx = cpx * inv_z;
        float pcy = cpy * inv_z;

        float gx = (pcx * (1.0f / (float)(W - 1)) - 0.5f) * 2.0f;
        float gy = (pcy * (1.0f / (float)(H - 1)) - 0.5f) * 2.0f;
        float xf = (gx + 1.0f) * (float)W * 0.5f - 0.5f;
        float yf = (gy + 1.0f) * (float)H * 0.5f - 0.5f;

        float x0f = floorf(xf);
        float y0f = floorf(yf);
        float wx = xf - x0f;
        float wy = yf - y0f;

        int ix0 = (int)x0f;
        int iy0 = (int)y0f;
        int ix1 = min(max(ix0 + 1, 0), W - 1);
        int iy1 = min(max(iy0 + 1, 0), H - 1);
        ix0 = min(max(ix0, 0), W - 1);
        iy0 = min(max(iy0, 0), H - 1);

        // translate to tile coordinates (clamped: memory-safety net)
        int sx0 = min(max(ix0 - xs0, 0), SRC_COLS - 1);
        int sx1 = min(max(ix1 - xs0, 0), SRC_COLS - 1);
        int sy0 = min(max(iy0 - ys0, 0), SRC_ROWS - 1);
        int sy1 = min(max(iy1 - ys0, 0), SRC_ROWS - 1);

        float w00 = (1.0f - wx) * (1.0f - wy);
        float w01 = wx * (1.0f - wy);
        float w10 = (1.0f - wx) * wy;
        float w11 = wx * wy;

        acc0[i] = sImg[0][sy0][sx0] * w00 + sImg[0][sy0][sx1] * w01
                + sImg[0][sy1][sx0] * w10 + sImg[0][sy1][sx1] * w11;
        acc1[i] = sImg[1][sy0][sx0] * w00 + sImg[1][sy0][sx1] * w01
                + sImg[1][sy1][sx0] * w10 + sImg[1][sy1][sx1] * w11;
        acc2[i] = sImg[2][sy0][sx0] * w00 + sImg[2][sy0][sx1] * w01
                + sImg[2][sy1][sx0] * w10 + sImg[2][sy1][sx1] * w11;
    }

    float* outb = out + (size_t)b * CH * HW;
    *(float4*)(outb + rowoff)          = r0;
    *(float4*)(outb + HW + rowoff)     = r1;
    *(float4*)(outb + 2 * HW + rowoff) = r2;
}

extern "C" void kernel_launch(void* const* d_in, const int* in_sizes, int n_in,
                              void* d_out, int out_size) {
    const float* img  = (const float*)d_in[0];
    const float* disp = (const float*)d_in[1];
    const float* srcK = (const float*)d_in[2];
    const float* tgtK = (const float*)d_in[3];
    const float* tvec = (const float*)d_in[4];
    float* out = (float*)d_out;

    setup_params_kernel<<<1, BATCH>>>(srcK, tgtK, tvec);
    dim3 grid(W / TILE_W, H / TILE_H, BATCH);   // (10, 128, 8)
    synth_kernel<<<grid, 256>>>(img, disp, out);
}

// round 4
// speedup vs baseline: 1.3354x; 1.3354x over previous
#include <cuda_runtime.h>

#define BATCH 8
#define CH 3
#define H 1024
#define W 1280
#define HW (H * W)
#define EPS 1e-7f
#define MIN_DEPTH 10.0f
#define MAX_DEPTH 255.0f

#define TILE_W 128
#define TILE_H 8
#define SRC_ROWS 10           // global rows [yt-1 .. yt+8]
#define SRC_COLS 136          // global cols [xt-2 .. xt+133]
#define SRC_ELEMS (SRC_ROWS * SRC_COLS)   // 1360

// Per-batch fused parameters: M (9 floats) + c (3 floats)
__device__ float g_MC[BATCH * 12];

__global__ void setup_params_kernel(const float* __restrict__ srcK,
                                    const float* __restrict__ tgtK,
                                    const float* __restrict__ tvec) {
    int b = threadIdx.x;
    if (b >= BATCH) return;
    const float* S = srcK + b * 16;
    const float* T = tgtK + b * 16;
    const float* t = tvec + b * 3;

    float a00 = S[0], a01 = S[1], a02 = S[2];
    float a10 = S[4], a11 = S[5], a12 = S[6];
    float a20 = S[8], a21 = S[9], a22 = S[10];
    float det = a00 * (a11 * a22 - a12 * a21)
              - a01 * (a10 * a22 - a12 * a20)
              + a02 * (a10 * a21 - a11 * a20);
    float id = 1.0f / det;
    float i00 = (a11 * a22 - a12 * a21) * id;
    float i01 = (a02 * a21 - a01 * a22) * id;
    float i02 = (a01 * a12 - a02 * a11) * id;
    float i10 = (a12 * a20 - a10 * a22) * id;
    float i11 = (a00 * a22 - a02 * a20) * id;
    float i12 = (a02 * a10 - a00 * a12) * id;
    float i20 = (a10 * a21 - a11 * a20) * id;
    float i21 = (a01 * a20 - a00 * a21) * id;
    float i22 = (a00 * a11 - a01 * a10) * id;

    float k00 = T[0], k01 = T[1], k02 = T[2];
    float k10 = T[4], k11 = T[5], k12 = T[6];
    float k20 = T[8], k21 = T[9], k22 = T[10];

    float* P = g_MC + b * 12;
    P[0] = k00 * i00 + k01 * i10 + k02 * i20;
    P[1] = k00 * i01 + k01 * i11 + k02 * i21;
    P[2] = k00 * i02 + k01 * i12 + k02 * i22;
    P[3] = k10 * i00 + k11 * i10 + k12 * i20;
    P[4] = k10 * i01 + k11 * i11 + k12 * i21;
    P[5] = k10 * i02 + k11 * i12 + k12 * i22;
    P[6] = k20 * i00 + k21 * i10 + k22 * i20;
    P[7] = k20 * i01 + k21 * i11 + k22 * i21;
    P[8] = k20 * i02 + k21 * i12 + k22 * i22;
    P[9]  = k00 * t[0] + k01 * t[1] + k02 * t[2];
    P[10] = k10 * t[0] + k11 * t[1] + k12 * t[2];
    P[11] = k20 * t[0] + k21 * t[1] + k22 * t[2];
}

// grid: (W/TILE_W, H/TILE_H, BATCH), block 256 = 128 cols x 2 rows, 4 row-iters/thread.
__global__ __launch_bounds__(256) void synth_kernel(const float* __restrict__ img,
                                                    const float* __restrict__ disp,
                                                    float* __restrict__ out) {
    __shared__ float sImg[CH * SRC_ELEMS];   // channel stride 1360 floats
    __shared__ float sP[12];

    const int b  = blockIdx.z;
    const int yt = blockIdx.y * TILE_H;
    const int xt = blockIdx.x * TILE_W;
    const int tid = threadIdx.x;

    const int ys0 = yt - 1;
    const int xs0 = xt - 2;

    if (tid < 12) sP[tid] = g_MC[b * 12 + tid];

    // ---- Stage source tile (+halo), border-replicated ----
    const float* imb = img + (size_t)b * CH * HW;
#pragma unroll
    for (int ch = 0; ch < CH; ch++) {
        const float* p = imb + ch * HW;
        float* s = sImg + ch * SRC_ELEMS;
        for (int idx = tid; idx < SRC_ELEMS; idx += 256) {
            int r = idx / SRC_COLS;          // const-div -> mul/shift
            int c = idx - r * SRC_COLS;
            int gy = min(max(ys0 + r, 0), H - 1);
            int gx = min(max(xs0 + c, 0), W - 1);
            s[idx] = __ldg(p + gy * W + gx);
        }
    }
    __syncthreads();

    const float m0 = sP[0], m1 = sP[1], m2 = sP[2];
    const float m3 = sP[3], m4 = sP[4], m5 = sP[5];
    const float m6 = sP[6], m7 = sP[7], m8 = sP[8];
    const float c0 = sP[9], c1 = sP[10], c2 = sP[11];

    const int lx = tid & (TILE_W - 1);       // 0..127, adjacent lanes -> adjacent x
    const int r0 = tid >> 7;                 // 0 or 1
    const int x  = xt + lx;
    const float fx = (float)x;

    // x-dependent projection terms (fixed per thread)
    const float tx_x = m0 * fx + m2;
    const float tx_y = m3 * fx + m5;
    const float tx_z = m6 * fx + m8;

    const float min_disp = 1.0f / MAX_DEPTH;
    const float max_disp = 1.0f / MIN_DEPTH;
    const float SXW = (float)W / (float)(W - 1);   // xf = pcx*SXW - 0.5
    const float SYH = (float)H / (float)(H - 1);

    const float* dbase = disp + (size_t)b * HW;
    float* outb = out + (size_t)b * CH * HW;

#pragma unroll
    for (int rr = r0; rr < TILE_H; rr += 2) {
        const int y = yt + rr;
        const float fy = (float)y;
        const int gidx = y * W + x;

        float d = __ldg(dbase + gidx);
        float depth = __fdividef(1.0f, min_disp + (max_disp - min_disp) * d);

        float cpx = depth * (m1 * fy + tx_x) + c0;
        float cpy = depth * (m4 * fy + tx_y) + c1;
        float cpz = depth * (m7 * fy + tx_z) + c2;

        float inv_z = __fdividef(1.0f, cpz + EPS);
        float xf = (cpx * inv_z) * SXW - 0.5f;
        float yf = (cpy * inv_z) * SYH - 0.5f;

        int ix0 = __float2int_rd(xf);
        int iy0 = __float2int_rd(yf);
        float wx = xf - (float)ix0;
        float wy = yf - (float)iy0;

        // tile coords; bounds proven by warp-field analysis, clamp = safety net
        int sx0 = min(max(ix0 - xs0, 0), SRC_COLS - 2);
        int sy0 = min(max(iy0 - ys0, 0), SRC_ROWS - 2);

        float iwx = 1.0f - wx;
        float iwy = 1.0f - wy;
        float w00 = iwx * iwy;
        float w01 = wx * iwy;
        float w10 = iwx * wy;
        float w11 = wx * wy;

        const float* s00 = sImg + sy0 * SRC_COLS + sx0;

        float v0 = s00[0] * w00 + s00[1] * w01
                 + s00[SRC_COLS] * w10 + s00[SRC_COLS + 1] * w11;
        float v1 = s00[SRC_ELEMS] * w00 + s00[SRC_ELEMS + 1] * w01
                 + s00[SRC_ELEMS + SRC_COLS] * w10 + s00[SRC_ELEMS + SRC_COLS + 1] * w11;
        float v2 = s00[2 * SRC_ELEMS] * w00 + s00[2 * SRC_ELEMS + 1] * w01
                 + s00[2 * SRC_ELEMS + SRC_COLS] * w10 + s00[2 * SRC_ELEMS + SRC_COLS + 1] * w11;

        outb[gidx] = v0;
        outb[HW + gidx] = v1;
        outb[2 * HW + gidx] = v2;
    }
}

extern "C" void kernel_launch(void* const* d_in, const int* in_sizes, int n_in,
                              void* d_out, int out_size) {
    const float* img  = (const float*)d_in[0];
    const float* disp = (const float*)d_in[1];
    const float* srcK = (const float*)d_in[2];
    const float* tgtK = (const float*)d_in[3];
    const float* tvec = (const float*)d_in[4];
    float* out = (float*)d_out;

    setup_params_kernel<<<1, BATCH>>>(srcK, tgtK, tvec);
    dim3 grid(W / TILE_W, H / TILE_H, BATCH);   // (10, 128, 8)
    synth_kernel<<<grid, 256>>>(img, disp, out);
}

// round 5
// speedup vs baseline: 2.0110x; 1.5060x over previous
#include <cuda_runtime.h>

#define BATCH 8
#define CH 3
#define H 1024
#define W 1280
#define HW (H * W)
#define EPS 1e-7f
#define MIN_DEPTH 10.0f
#define MAX_DEPTH 255.0f

#define TILE_W 128
#define TILE_H 8

// Per-batch fused parameters: M (9 floats) + c (3 floats)
__device__ float g_MC[BATCH * 12];

__global__ void setup_params_kernel(const float* __restrict__ srcK,
                                    const float* __restrict__ tgtK,
                                    const float* __restrict__ tvec) {
    int b = threadIdx.x;
    if (b >= BATCH) return;
    const float* S = srcK + b * 16;
    const float* T = tgtK + b * 16;
    const float* t = tvec + b * 3;

    float a00 = S[0], a01 = S[1], a02 = S[2];
    float a10 = S[4], a11 = S[5], a12 = S[6];
    float a20 = S[8], a21 = S[9], a22 = S[10];
    float det = a00 * (a11 * a22 - a12 * a21)
              - a01 * (a10 * a22 - a12 * a20)
              + a02 * (a10 * a21 - a11 * a20);
    float id = 1.0f / det;
    float i00 = (a11 * a22 - a12 * a21) * id;
    float i01 = (a02 * a21 - a01 * a22) * id;
    float i02 = (a01 * a12 - a02 * a11) * id;
    float i10 = (a12 * a20 - a10 * a22) * id;
    float i11 = (a00 * a22 - a02 * a20) * id;
    float i12 = (a02 * a10 - a00 * a12) * id;
    float i20 = (a10 * a21 - a11 * a20) * id;
    float i21 = (a01 * a20 - a00 * a21) * id;
    float i22 = (a00 * a11 - a01 * a10) * id;

    float k00 = T[0], k01 = T[1], k02 = T[2];
    float k10 = T[4], k11 = T[5], k12 = T[6];
    float k20 = T[8], k21 = T[9], k22 = T[10];

    float* P = g_MC + b * 12;
    P[0] = k00 * i00 + k01 * i10 + k02 * i20;
    P[1] = k00 * i01 + k01 * i11 + k02 * i21;
    P[2] = k00 * i02 + k01 * i12 + k02 * i22;
    P[3] = k10 * i00 + k11 * i10 + k12 * i20;
    P[4] = k10 * i01 + k11 * i11 + k12 * i21;
    P[5] = k10 * i02 + k11 * i12 + k12 * i22;
    P[6] = k20 * i00 + k21 * i10 + k22 * i20;
    P[7] = k20 * i01 + k21 * i11 + k22 * i21;
    P[8] = k20 * i02 + k21 * i12 + k22 * i22;
    P[9]  = k00 * t[0] + k01 * t[1] + k02 * t[2];
    P[10] = k10 * t[0] + k11 * t[1] + k12 * t[2];
    P[11] = k20 * t[0] + k21 * t[1] + k22 * t[2];
}

// grid: (W/TILE_W, H/TILE_H, BATCH), block 256 = 128 cols x 2 rows; 4 rows/thread.
// 1 px/thread-iteration, adjacent lanes -> adjacent x (min L1 wavefronts/gather).
__global__ __launch_bounds__(256) void synth_kernel(const float* __restrict__ img,
                                                    const float* __restrict__ disp,
                                                    float* __restrict__ out) {
    __shared__ float sP[12];

    const int b  = blockIdx.z;
    const int yt = blockIdx.y * TILE_H;
    const int xt = blockIdx.x * TILE_W;
    const int tid = threadIdx.x;

    if (tid < 12) sP[tid] = g_MC[b * 12 + tid];
    __syncthreads();

    const float m0 = sP[0], m1 = sP[1], m2 = sP[2];
    const float m3 = sP[3], m4 = sP[4], m5 = sP[5];
    const float m6 = sP[6], m7 = sP[7], m8 = sP[8];
    const float c0 = sP[9], c1 = sP[10], c2 = sP[11];

    const int lx = tid & (TILE_W - 1);   // adjacent lanes -> adjacent x
    const int r0 = tid >> 7;             // 0 or 1
    const int x  = xt + lx;
    const float fx = (float)x;

    // x-dependent projection terms (fixed per thread)
    const float tx_x = m0 * fx + m2;
    const float tx_y = m3 * fx + m5;
    const float tx_z = m6 * fx + m8;

    const float min_disp = 1.0f / MAX_DEPTH;
    const float max_disp = 1.0f / MIN_DEPTH;
    const float SXW = (float)W / (float)(W - 1);
    const float SYH = (float)H / (float)(H - 1);

    const float* dbase = disp + (size_t)b * HW;
    const float* imb   = img  + (size_t)b * CH * HW;
    float* outb        = out  + (size_t)b * CH * HW;

    int gidx = (yt + r0) * W + x;

#pragma unroll
    for (int k = 0; k < TILE_H / 2; k++, gidx += 2 * W) {
        const int y = yt + r0 + 2 * k;
        const float fy = (float)y;

        float d = __ldg(dbase + gidx);
        float depth = __fdividef(1.0f, min_disp + (max_disp - min_disp) * d);

        float cpx = depth * (m1 * fy + tx_x) + c0;
        float cpy = depth * (m4 * fy + tx_y) + c1;
        float cpz = depth * (m7 * fy + tx_z) + c2;

        float inv_z = __fdividef(1.0f, cpz + EPS);
        float xf = (cpx * inv_z) * SXW - 0.5f;
        float yf = (cpy * inv_z) * SYH - 0.5f;

        int ix0 = __float2int_rd(xf);
        int iy0 = __float2int_rd(yf);
        float wx = xf - (float)ix0;
        float wy = yf - (float)iy0;

        int ix1 = min(max(ix0 + 1, 0), W - 1);
        int iy1 = min(max(iy0 + 1, 0), H - 1);
        ix0 = min(max(ix0, 0), W - 1);
        iy0 = min(max(iy0, 0), H - 1);

        float iwx = 1.0f - wx;
        float iwy = 1.0f - wy;
        float w00 = iwx * iwy;
        float w01 = wx * iwy;
        float w10 = iwx * wy;
        float w11 = wx * wy;

        int o00 = iy0 * W + ix0;
        int dx  = ix1 - ix0;             // 0 or 1
        int dyW = (iy1 - iy0) * W;       // 0 or W
        int o01 = o00 + dx;
        int o10 = o00 + dyW;
        int o11 = o10 + dx;

        const float* p0 = imb;
        const float* p1 = imb + HW;
        const float* p2 = imb + 2 * HW;

        float v0 = __ldg(p0 + o00) * w00;
        float v1 = __ldg(p1 + o00) * w00;
        float v2 = __ldg(p2 + o00) * w00;
        v0 = fmaf(__ldg(p0 + o01), w01, v0);
        v1 = fmaf(__ldg(p1 + o01), w01, v1);
        v2 = fmaf(__ldg(p2 + o01), w01, v2);
        v0 = fmaf(__ldg(p0 + o10), w10, v0);
        v1 = fmaf(__ldg(p1 + o10), w10, v1);
        v2 = fmaf(__ldg(p2 + o10), w10, v2);
        v0 = fmaf(__ldg(p0 + o11), w11, v0);
        v1 = fmaf(__ldg(p1 + o11), w11, v1);
        v2 = fmaf(__ldg(p2 + o11), w11, v2);

        outb[gidx]          = v0;
        outb[HW + gidx]     = v1;
        outb[2 * HW + gidx] = v2;
    }
}

extern "C" void kernel_launch(void* const* d_in, const int* in_sizes, int n_in,
                              void* d_out, int out_size) {
    const float* img  = (const float*)d_in[0];
    const float* disp = (const float*)d_in[1];
    const float* srcK = (const float*)d_in[2];
    const float* tgtK = (const float*)d_in[3];
    const float* tvec = (const float*)d_in[4];
    float* out = (float*)d_out;

    setup_params_kernel<<<1, BATCH>>>(srcK, tgtK, tvec);
    dim3 grid(W / TILE_W, H / TILE_H, BATCH);   // (10, 128, 8)
    synth_kernel<<<grid, 256>>>(img, disp, out);
}

// round 6
// speedup vs baseline: 2.0719x; 1.0303x over previous
#include <cuda_runtime.h>

#define BATCH 8
#define CH 3
#define H 1024
#define W 1280
#define HW (H * W)
#define EPS 1e-7f
#define MIN_DEPTH 10.0f
#define MAX_DEPTH 255.0f

#define TILE_W 128
#define TILE_H 8
#define RPT 4                 // rows per thread

// Per-batch fused parameters: M (9 floats) + c (3 floats)
__device__ float g_MC[BATCH * 12];

__global__ void setup_params_kernel(const float* __restrict__ srcK,
                                    const float* __restrict__ tgtK,
                                    const float* __restrict__ tvec) {
    int b = threadIdx.x;
    if (b >= BATCH) return;
    const float* S = srcK + b * 16;
    const float* T = tgtK + b * 16;
    const float* t = tvec + b * 3;

    float a00 = S[0], a01 = S[1], a02 = S[2];
    float a10 = S[4], a11 = S[5], a12 = S[6];
    float a20 = S[8], a21 = S[9], a22 = S[10];
    float det = a00 * (a11 * a22 - a12 * a21)
              - a01 * (a10 * a22 - a12 * a20)
              + a02 * (a10 * a21 - a11 * a20);
    float id = 1.0f / det;
    float i00 = (a11 * a22 - a12 * a21) * id;
    float i01 = (a02 * a21 - a01 * a22) * id;
    float i02 = (a01 * a12 - a02 * a11) * id;
    float i10 = (a12 * a20 - a10 * a22) * id;
    float i11 = (a00 * a22 - a02 * a20) * id;
    float i12 = (a02 * a10 - a00 * a12) * id;
    float i20 = (a10 * a21 - a11 * a20) * id;
    float i21 = (a01 * a20 - a00 * a21) * id;
    float i22 = (a00 * a11 - a01 * a10) * id;

    float k00 = T[0], k01 = T[1], k02 = T[2];
    float k10 = T[4], k11 = T[5], k12 = T[6];
    float k20 = T[8], k21 = T[9], k22 = T[10];

    float* P = g_MC + b * 12;
    P[0] = k00 * i00 + k01 * i10 + k02 * i20;
    P[1] = k00 * i01 + k01 * i11 + k02 * i21;
    P[2] = k00 * i02 + k01 * i12 + k02 * i22;
    P[3] = k10 * i00 + k11 * i10 + k12 * i20;
    P[4] = k10 * i01 + k11 * i11 + k12 * i21;
    P[5] = k10 * i02 + k11 * i12 + k12 * i22;
    P[6] = k20 * i00 + k21 * i10 + k22 * i20;
    P[7] = k20 * i01 + k21 * i11 + k22 * i21;
    P[8] = k20 * i02 + k21 * i12 + k22 * i22;
    P[9]  = k00 * t[0] + k01 * t[1] + k02 * t[2];
    P[10] = k10 * t[0] + k11 * t[1] + k12 * t[2];
    P[11] = k20 * t[0] + k21 * t[1] + k22 * t[2];
}

// grid: (W/TILE_W, H/TILE_H, BATCH), block 256 = 128 cols x 2 rows; RPT rows/thread.
// Phase-split: all disp loads -> all coords -> all 48 gathers -> all FMAs -> stores.
__global__ __launch_bounds__(256) void synth_kernel(const float* __restrict__ img,
                                                    const float* __restrict__ disp,
                                                    float* __restrict__ out) {
    __shared__ float sP[12];

    const int b  = blockIdx.z;
    const int yt = blockIdx.y * TILE_H;
    const int xt = blockIdx.x * TILE_W;
    const int tid = threadIdx.x;

    if (tid < 12) sP[tid] = g_MC[b * 12 + tid];
    __syncthreads();

    const float m0 = sP[0], m1 = sP[1], m2 = sP[2];
    const float m3 = sP[3], m4 = sP[4], m5 = sP[5];
    const float m6 = sP[6], m7 = sP[7], m8 = sP[8];
    const float c0 = sP[9], c1 = sP[10], c2 = sP[11];

    const int lx = tid & (TILE_W - 1);   // adjacent lanes -> adjacent x
    const int rp = tid >> 7;             // 0 or 1
    const int x  = xt + lx;
    const float fx = (float)x;

    const float tx_x = m0 * fx + m2;
    const float tx_y = m3 * fx + m5;
    const float tx_z = m6 * fx + m8;

    const float min_disp = 1.0f / MAX_DEPTH;
    const float max_disp = 1.0f / MIN_DEPTH;
    const float SXW = (float)W / (float)(W - 1);
    const float SYH = (float)H / (float)(H - 1);

    const float* dbase = disp + (size_t)b * HW;
    const float* imb   = img  + (size_t)b * CH * HW;
    float* outb        = out  + (size_t)b * CH * HW;

    const int gidx0 = (yt + rp) * W + x;

    // ---- Phase 1: all disp loads (independent) ----
    float dval[RPT];
#pragma unroll
    for (int k = 0; k < RPT; k++)
        dval[k] = __ldg(dbase + gidx0 + k * 2 * W);

    // ---- Phase 2: all coordinates / weights / tap offsets ----
    int   o00[RPT], odx[RPT], ody[RPT];
    float w00[RPT], w01[RPT], w10[RPT], w11[RPT];
#pragma unroll
    for (int k = 0; k < RPT; k++) {
        const float fy = (float)(yt + rp + 2 * k);
        float depth = __fdividef(1.0f, min_disp + (max_disp - min_disp) * dval[k]);

        float cpx = depth * (m1 * fy + tx_x) + c0;
        float cpy = depth * (m4 * fy + tx_y) + c1;
        float cpz = depth * (m7 * fy + tx_z) + c2;

        float inv_z = __fdividef(1.0f, cpz + EPS);
        float xf = (cpx * inv_z) * SXW - 0.5f;
        float yf = (cpy * inv_z) * SYH - 0.5f;

        int ix0 = __float2int_rd(xf);
        int iy0 = __float2int_rd(yf);
        float wx = xf - (float)ix0;
        float wy = yf - (float)iy0;

        int ix1 = min(max(ix0 + 1, 0), W - 1);
        int iy1 = min(max(iy0 + 1, 0), H - 1);
        ix0 = min(max(ix0, 0), W - 1);
        iy0 = min(max(iy0, 0), H - 1);

        float iwx = 1.0f - wx;
        float iwy = 1.0f - wy;
        w00[k] = iwx * iwy;
        w01[k] = wx * iwy;
        w10[k] = iwx * wy;
        w11[k] = wx * wy;

        o00[k] = iy0 * W + ix0;
        odx[k] = ix1 - ix0;              // 0 or 1
        ody[k] = (iy1 - iy0) * W;        // 0 or W
    }

    // ---- Phase 3: all gathers (channel offsets folded as LDG immediates) ----
    float t00[RPT][CH], t01[RPT][CH], t10[RPT][CH], t11[RPT][CH];
#pragma unroll
    for (int k = 0; k < RPT; k++) {
        const float* a00 = imb + o00[k];
        const float* a01 = a00 + odx[k];
        const float* a10 = a00 + ody[k];
        const float* a11 = a10 + odx[k];
#pragma unroll
        for (int ch = 0; ch < CH; ch++) {
            t00[k][ch] = __ldg(a00 + ch * HW);
            t01[k][ch] = __ldg(a01 + ch * HW);
            t10[k][ch] = __ldg(a10 + ch * HW);
            t11[k][ch] = __ldg(a11 + ch * HW);
        }
    }

    // ---- Phase 4: blend + store ----
#pragma unroll
    for (int k = 0; k < RPT; k++) {
        const int gidx = gidx0 + k * 2 * W;
#pragma unroll
        for (int ch = 0; ch < CH; ch++) {
            float v = t00[k][ch] * w00[k];
            v = fmaf(t01[k][ch], w01[k], v);
            v = fmaf(t10[k][ch], w10[k], v);
            v = fmaf(t11[k][ch], w11[k], v);
            outb[ch * HW + gidx] = v;
        }
    }
}

extern "C" void kernel_launch(void* const* d_in, const int* in_sizes, int n_in,
                              void* d_out, int out_size) {
    const float* img  = (const float*)d_in[0];
    const float* disp = (const float*)d_in[1];
    const float* srcK = (const float*)d_in[2];
    const float* tgtK = (const float*)d_in[3];
    const float* tvec = (const float*)d_in[4];
    float* out = (float*)d_out;

    setup_params_kernel<<<1, BATCH>>>(srcK, tgtK, tvec);
    dim3 grid(W / TILE_W, H / TILE_H, BATCH);   // (10, 128, 8)
    synth_kernel<<<grid, 256>>>(img, disp, out);
}